// round 1
// baseline (speedup 1.0000x reference)
#include <cuda_runtime.h>
#include <math_constants.h>

#define BN   8
#define BC   256
#define BNF  16
#define BWH  784           // 28*28
#define CSTR (BNF*BWH)     // 12544 : stride between channels in l
#define NTHR 1024
#define NCG  8             // channel groups in phase 1
#define CPG  (BC/NCG)      // 32 channels per group

__global__ __launch_bounds__(NTHR, 1)
void mfla_kernel(const float* __restrict__ l,
                 const float* __restrict__ g,
                 const float* __restrict__ w,
                 float* __restrict__ outc,   // [N,NF,W,H]
                 float* __restrict__ outg)   // [N,C,NF]
{
    __shared__ float sw[BC];
    __shared__ float part[NCG * BWH];
    __shared__ __align__(16) float sc[BWH];
    __shared__ float red[32];
    __shared__ float s_gdot, s_max, s_inv;

    const int tid  = threadIdx.x;
    const int n    = blockIdx.x >> 4;   // / NF
    const int f    = blockIdx.x & 15;   // % NF
    const float* lb = l + ((size_t)n * BC * BNF + f) * BWH;   // l[n][c][f][wh] = lb[c*CSTR + wh]

    // ---- load weights to smem + compute gdot = sum_c g[n,c]*w[c] ----
    float p = 0.f;
    if (tid < BC) {
        float wv = w[tid];
        sw[tid] = wv;
        p = g[n * BC + tid] * wv;
    }
    #pragma unroll
    for (int o = 16; o; o >>= 1) p += __shfl_xor_sync(0xffffffffu, p, o);
    if ((tid & 31) == 0) red[tid >> 5] = p;
    __syncthreads();
    if (tid < 32) {
        float v = red[tid];
        #pragma unroll
        for (int o = 16; o; o >>= 1) v += __shfl_xor_sync(0xffffffffu, v, o);
        if (tid == 0) s_gdot = v;
    }
    __syncthreads();

    // ---- Phase 1: partial channel dots. 8 c-groups x 128 wh-lanes ----
    {
        const int cg = tid >> 7;       // 0..7
        const int wl = tid & 127;      // 0..127
        const int c0 = cg * CPG;
        for (int wh = wl; wh < BWH; wh += 128) {
            const float* lp = lb + (size_t)c0 * CSTR + wh;
            float acc = 0.f;
            #pragma unroll 8
            for (int c = 0; c < CPG; ++c)
                acc = fmaf(lp[(size_t)c * CSTR], sw[c0 + c], acc);
            part[cg * BWH + wh] = acc;
        }
    }
    __syncthreads();

    // ---- Phase 1b: combine partials, add gdot, write c output, stash in smem ----
    {
        float* cout = outc + ((size_t)n * BNF + f) * BWH;
        const float gd = s_gdot;
        for (int wh = tid; wh < BWH; wh += NTHR) {
            float v = gd;
            #pragma unroll
            for (int k = 0; k < NCG; ++k) v += part[k * BWH + wh];
            sc[wh]   = v;
            cout[wh] = v;
        }
    }
    __syncthreads();

    // ---- Phase 2: softmax over 784 (max, exp, sum; keep unnormalized e) ----
    {
        float m = -CUDART_INF_F;
        for (int wh = tid; wh < BWH; wh += NTHR) m = fmaxf(m, sc[wh]);
        #pragma unroll
        for (int o = 16; o; o >>= 1) m = fmaxf(m, __shfl_xor_sync(0xffffffffu, m, o));
        if ((tid & 31) == 0) red[tid >> 5] = m;
        __syncthreads();
        if (tid < 32) {
            float v = red[tid];
            #pragma unroll
            for (int o = 16; o; o >>= 1) v = fmaxf(v, __shfl_xor_sync(0xffffffffu, v, o));
            if (tid == 0) s_max = v;
        }
        __syncthreads();

        const float ms = s_max;
        float s = 0.f;
        for (int wh = tid; wh < BWH; wh += NTHR) {
            float e = __expf(sc[wh] - ms);
            sc[wh] = e;
            s += e;
        }
        #pragma unroll
        for (int o = 16; o; o >>= 1) s += __shfl_xor_sync(0xffffffffu, s, o);
        if ((tid & 31) == 0) red[tid >> 5] = s;
        __syncthreads();
        if (tid < 32) {
            float v = red[tid];
            #pragma unroll
            for (int o = 16; o; o >>= 1) v += __shfl_xor_sync(0xffffffffu, v, o);
            if (tid == 0) s_inv = 1.0f / v;
        }
        __syncthreads();
    }

    // ---- Phase 3: g_out[n,c,f] = inv * sum_wh e[wh] * l[c,wh] (float4, L2-hot) ----
    {
        const int warp = tid >> 5;
        const int lane = tid & 31;
        const float inv = s_inv;
        const float4* scv = reinterpret_cast<const float4*>(sc);
        for (int c = warp; c < BC; c += 32) {
            const float4* lv = reinterpret_cast<const float4*>(lb + (size_t)c * CSTR);
            float acc = 0.f;
            #pragma unroll 2
            for (int i = lane; i < BWH / 4; i += 32) {
                float4 a4 = scv[i];
                float4 l4 = lv[i];
                acc += a4.x * l4.x + a4.y * l4.y + a4.z * l4.z + a4.w * l4.w;
            }
            #pragma unroll
            for (int o = 16; o; o >>= 1) acc += __shfl_xor_sync(0xffffffffu, acc, o);
            if (lane == 0)
                outg[((size_t)n * BC + c) * BNF + f] = acc * inv;
        }
    }
}

extern "C" void kernel_launch(void* const* d_in, const int* in_sizes, int n_in,
                              void* d_out, int out_size)
{
    const float* l = (const float*)d_in[0];
    const float* g = (const float*)d_in[1];
    const float* w = (const float*)d_in[2];
    float* out  = (float*)d_out;
    float* outc = out;                              // [8,16,28,28] = 100352 floats
    float* outg = out + (size_t)BN * BNF * BWH;     // [8,256,16]   = 32768 floats

    mfla_kernel<<<BN * BNF, NTHR>>>(l, g, w, outc, outg);
}